// round 1
// baseline (speedup 1.0000x reference)
#include <cuda_runtime.h>
#include <math.h>

#define B_  8
#define T_  4096
#define W_  1024
#define H_  8
#define BW_ 128
#define NC  64
#define TC  (T_ / NC)   // 64

// Scratch (static device globals; no runtime allocation)
__device__ float g_A [(size_t)B_ * T_ * W_];   // decay a, then overwritten with prefix products P
__device__ float g_NX[(size_t)B_ * T_ * W_];   // norm_x
__device__ float g_Aprod[B_ * NC * W_];
__device__ float g_hlast[B_ * NC * W_];
__device__ float g_carry[B_ * NC * W_];

// ---------------------------------------------------------------------------
// Kernel 1: block-diagonal gates. Grid (512 row-tiles, 8 heads), 256 threads.
// Block tile: 64 rows x 128 cols, both gate GEMMs. Thread tile: 4 rows x 8 cols x 2.
// smem: x tile (32KB) + w_in (64KB) + w_a (64KB) = 160KB dynamic.
// ---------------------------------------------------------------------------
__global__ void __launch_bounds__(256) gates_kernel(
    const float* __restrict__ x, const float* __restrict__ w_in,
    const float* __restrict__ b_in, const float* __restrict__ w_a,
    const float* __restrict__ b_a, const float* __restrict__ a_param)
{
    extern __shared__ float sm[];
    float* x_s  = sm;                   // 64*128
    float* w1_s = sm + 64 * 128;        // 128*128
    float* w2_s = w1_s + 128 * 128;     // 128*128

    const int h    = blockIdx.y;
    const int row0 = blockIdx.x * 64;
    const int tid  = threadIdx.x;

    // load x tile [64][128] (float4, coalesced)
    for (int idx = tid; idx < 64 * 32; idx += 256) {
        int r = idx >> 5, c4 = idx & 31;
        *(float4*)&x_s[r * 128 + c4 * 4] =
            *(const float4*)&x[(size_t)(row0 + r) * W_ + h * BW_ + c4 * 4];
    }
    const float* w1g = w_in + h * BW_ * BW_;
    const float* w2g = w_a  + h * BW_ * BW_;
    for (int idx = tid; idx < 128 * 32; idx += 256) {
        int i = idx >> 5, j4 = idx & 31;
        *(float4*)&w1_s[i * 128 + j4 * 4] = *(const float4*)&w1g[i * 128 + j4 * 4];
        *(float4*)&w2_s[i * 128 + j4 * 4] = *(const float4*)&w2g[i * 128 + j4 * 4];
    }
    __syncthreads();

    const int tx = tid & 15, ty = tid >> 4;
    const int c0 = tx * 8,   r0 = ty * 4;

    float a1[4][8], a2[4][8];
    #pragma unroll
    for (int r = 0; r < 4; r++)
        #pragma unroll
        for (int c = 0; c < 8; c++) { a1[r][c] = 0.f; a2[r][c] = 0.f; }

    for (int k = 0; k < 128; k += 4) {
        float4 xv[4];
        #pragma unroll
        for (int r = 0; r < 4; r++)
            xv[r] = *(const float4*)&x_s[(r0 + r) * 128 + k];
        #pragma unroll
        for (int kk = 0; kk < 4; kk++) {
            float4 wA = *(const float4*)&w1_s[(k + kk) * 128 + c0];
            float4 wB = *(const float4*)&w1_s[(k + kk) * 128 + c0 + 4];
            float4 wC = *(const float4*)&w2_s[(k + kk) * 128 + c0];
            float4 wD = *(const float4*)&w2_s[(k + kk) * 128 + c0 + 4];
            #pragma unroll
            for (int r = 0; r < 4; r++) {
                float xr = ((const float*)&xv[r])[kk];
                a1[r][0] += xr * wA.x; a1[r][1] += xr * wA.y;
                a1[r][2] += xr * wA.z; a1[r][3] += xr * wA.w;
                a1[r][4] += xr * wB.x; a1[r][5] += xr * wB.y;
                a1[r][6] += xr * wB.z; a1[r][7] += xr * wB.w;
                a2[r][0] += xr * wC.x; a2[r][1] += xr * wC.y;
                a2[r][2] += xr * wC.z; a2[r][3] += xr * wC.w;
                a2[r][4] += xr * wD.x; a2[r][5] += xr * wD.y;
                a2[r][6] += xr * wD.z; a2[r][7] += xr * wD.w;
            }
        }
    }

    // epilogue: gates -> a, norm_x
    float sc[8], b1c[8], b2c[8];
    #pragma unroll
    for (int c = 0; c < 8; c++) {
        int wch = h * BW_ + c0 + c;
        sc[c]  = log1pf(expf(a_param[wch]));  // softplus
        b1c[c] = b_in[wch];
        b2c[c] = b_a[wch];
    }
    #pragma unroll
    for (int r = 0; r < 4; r++) {
        int row = row0 + r0 + r;
        int t   = row & (T_ - 1);
        size_t base = (size_t)row * W_ + h * BW_ + c0;
        #pragma unroll
        for (int c = 0; c < 8; c++) {
            float gx = 1.f / (1.f + expf(-(a1[r][c] + b1c[c])));
            float ga = 1.f / (1.f + expf(-(a2[r][c] + b2c[c])));
            float la = -8.f * ga * sc[c];
            float av = expf(la);
            float mult = sqrtf(fmaxf(0.f, 1.f - expf(2.f * la)));
            if (t == 0) { av = 0.f; mult = 1.f; }
            float nx = x_s[(r0 + r) * 128 + c0 + c] * gx * mult;
            g_A [base + c] = av;
            g_NX[base + c] = nx;
        }
    }
}

// ---------------------------------------------------------------------------
// Kernel 2: chunk-local scan. Grid (NC chunks, B), 1024 threads (one per channel).
// Writes local scan into y, overwrites g_A with inclusive prefix products.
// ---------------------------------------------------------------------------
__global__ void __launch_bounds__(1024) scan_kernel(float* __restrict__ y)
{
    const int c  = blockIdx.x;
    const int b  = blockIdx.y;
    const int ch = threadIdx.x;
    size_t base = ((size_t)b * T_ + (size_t)c * TC) * W_ + ch;

    float hv = 0.f, ap = 1.f;
    #pragma unroll 4
    for (int t = 0; t < TC; t++) {
        size_t idx = base + (size_t)t * W_;
        float a  = g_A[idx];
        float nx = g_NX[idx];
        hv = fmaf(a, hv, nx);
        ap *= a;
        y[idx]   = hv;
        g_A[idx] = ap;   // prefix product P_t (inclusive within chunk)
    }
    int sidx = (b * NC + c) * W_ + ch;
    g_Aprod[sidx] = ap;
    g_hlast[sidx] = hv;
}

// ---------------------------------------------------------------------------
// Kernel 3: exclusive carry scan across chunks. Grid (B), 1024 threads.
// ---------------------------------------------------------------------------
__global__ void __launch_bounds__(1024) carry_kernel()
{
    const int b = blockIdx.x;
    const int ch = threadIdx.x;
    float carry = 0.f;
    for (int c = 0; c < NC; c++) {
        int sidx = (b * NC + c) * W_ + ch;
        g_carry[sidx] = carry;
        carry = fmaf(g_Aprod[sidx], carry, g_hlast[sidx]);
    }
}

// ---------------------------------------------------------------------------
// Kernel 4: apply carries. Grid (NC-1, B) (chunk 0 has zero carry), 1024 thr.
// ---------------------------------------------------------------------------
__global__ void __launch_bounds__(1024) apply_kernel(float* __restrict__ y)
{
    const int c  = blockIdx.x + 1;
    const int b  = blockIdx.y;
    const int ch = threadIdx.x;
    float carry = g_carry[(b * NC + c) * W_ + ch];
    size_t base = ((size_t)b * T_ + (size_t)c * TC) * W_ + ch;
    #pragma unroll 4
    for (int t = 0; t < TC; t++) {
        size_t idx = base + (size_t)t * W_;
        y[idx] = fmaf(g_A[idx], carry, y[idx]);
    }
}

// ---------------------------------------------------------------------------
extern "C" void kernel_launch(void* const* d_in, const int* in_sizes, int n_in,
                              void* d_out, int out_size)
{
    const float* x       = (const float*)d_in[0];
    const float* w_in    = (const float*)d_in[1];
    const float* b_in    = (const float*)d_in[2];
    const float* w_a     = (const float*)d_in[3];
    const float* b_a     = (const float*)d_in[4];
    const float* a_param = (const float*)d_in[5];
    float* y = (float*)d_out;

    const int smem = (64 * 128 + 2 * 128 * 128) * sizeof(float);  // 160 KB
    cudaFuncSetAttribute(gates_kernel,
                         cudaFuncAttributeMaxDynamicSharedMemorySize, smem);

    gates_kernel<<<dim3((B_ * T_) / 64, H_), 256, smem>>>(x, w_in, b_in, w_a, b_a, a_param);
    scan_kernel <<<dim3(NC, B_), 1024>>>(y);
    carry_kernel<<<B_, 1024>>>();
    apply_kernel<<<dim3(NC - 1, B_), 1024>>>(y);
}

// round 3
// speedup vs baseline: 2.6614x; 2.6614x over previous
#include <cuda_runtime.h>
#include <cuda_bf16.h>
#include <cstdint>
#include <math.h>

#define B_  8
#define T_  4096
#define W_  1024
#define H_  8
#define NC  64
#define TC  64   // T_/NC

// ---------------- scratch (static device globals) ----------------
__device__ float g_A [(size_t)B_ * T_ * W_];   // decay a -> prefix products P
__device__ float g_NX[(size_t)B_ * T_ * W_];   // norm_x
__device__ float g_Aprod[B_ * NC * W_];
__device__ float g_hlast[B_ * NC * W_];
__device__ float g_carry[B_ * NC * W_];

// ---------------- smem layout (bytes) ----------------
#define SX        136                      // padded row stride in bf16 elems (conflict-free ldmatrix)
#define XTILE_B   (64 * SX * 2)            // 17408
#define WTILE_B   (128 * SX * 2)           // 34816
#define SM_XH     0
#define SM_XL     (SM_XH + XTILE_B)
#define SM_W1H    (SM_XL + XTILE_B)        // 34816
#define SM_W1L    (SM_W1H + WTILE_B)
#define SM_W2H    (SM_W1L + WTILE_B)
#define SM_W2L    (SM_W2H + WTILE_B)
#define SM_SC     (SM_W2L + WTILE_B)       // 174080
#define SM_B1     (SM_SC + 512)
#define SM_B2     (SM_B1 + 512)
#define SM_TOTAL  (SM_B2 + 512)            // 175616

__device__ __forceinline__ uint32_t smem_u32(const void* p) {
    uint32_t a;
    asm("{ .reg .u64 t; cvta.to.shared.u64 t, %1; cvt.u32.u64 %0, t; }" : "=r"(a) : "l"(p));
    return a;
}
__device__ __forceinline__ void ldm_x4(uint32_t* r, uint32_t addr) {
    asm volatile("ldmatrix.sync.aligned.m8n8.x4.shared.b16 {%0,%1,%2,%3}, [%4];"
        : "=r"(r[0]), "=r"(r[1]), "=r"(r[2]), "=r"(r[3]) : "r"(addr));
}
__device__ __forceinline__ void ldm_x4_t(uint32_t* r, uint32_t addr) {
    asm volatile("ldmatrix.sync.aligned.m8n8.x4.trans.shared.b16 {%0,%1,%2,%3}, [%4];"
        : "=r"(r[0]), "=r"(r[1]), "=r"(r[2]), "=r"(r[3]) : "r"(addr));
}
__device__ __forceinline__ void mma16816(float* c, const uint32_t* a, const uint32_t* b) {
    asm volatile("mma.sync.aligned.m16n8k16.row.col.f32.bf16.bf16.f32 "
        "{%0,%1,%2,%3}, {%4,%5,%6,%7}, {%8,%9}, {%0,%1,%2,%3};"
        : "+f"(c[0]), "+f"(c[1]), "+f"(c[2]), "+f"(c[3])
        : "r"(a[0]), "r"(a[1]), "r"(a[2]), "r"(a[3]), "r"(b[0]), "r"(b[1]));
}
__device__ __forceinline__ float sigm(float v) {
    return __fdividef(1.f, 1.f + __expf(-v));
}
__device__ __forceinline__ float sqrt_ap(float v) {
    float r; asm("sqrt.approx.f32 %0, %1;" : "=f"(r) : "f"(v)); return r;
}
__device__ __forceinline__ uint32_t pack2(float a, float b) {
    __nv_bfloat162 t; t.x = __float2bfloat16(a); t.y = __float2bfloat16(b);
    return *(uint32_t*)&t;
}
__device__ __forceinline__ uint32_t pack2lo(float a, float ha, float b, float hb) {
    __nv_bfloat162 t; t.x = __float2bfloat16(a - ha); t.y = __float2bfloat16(b - hb);
    return *(uint32_t*)&t;
}

// ---------------------------------------------------------------------------
// gates kernel: block = (row-chunk of 512, head). 256 threads (8 warps).
// Weights converted to bf16 hi/lo in smem once; 8 x-tiles of 64 rows looped.
// Warp tile: 32 rows x 32 cols, both gemms, split-bf16 (3 mma passes).
// ---------------------------------------------------------------------------
__global__ void __launch_bounds__(256, 1) gates_kernel(
    const float* __restrict__ x, const float* __restrict__ w_in,
    const float* __restrict__ b_in, const float* __restrict__ w_a,
    const float* __restrict__ b_a, const float* __restrict__ a_param)
{
    extern __shared__ char sm[];
    const int tid = threadIdx.x, wid = tid >> 5, lane = tid & 31;
    const int h = blockIdx.y;
    const int row0 = blockIdx.x * 512;

    float* scv = (float*)(sm + SM_SC);
    float* b1v = (float*)(sm + SM_B1);
    float* b2v = (float*)(sm + SM_B2);

    // ---- convert weights fp32 -> bf16 hi/lo into padded smem [K][N] ----
    #pragma unroll
    for (int g = 0; g < 2; g++) {
        const float* wsrc = (g ? w_a : w_in) + h * 16384;
        char* WH = sm + (g ? SM_W2H : SM_W1H);
        char* WL = sm + (g ? SM_W2L : SM_W1L);
        for (int idx = tid; idx < 4096; idx += 256) {
            int k = idx >> 5, n4 = (idx & 31) * 4;
            float4 v = *(const float4*)&wsrc[k * 128 + n4];
            uint32_t off = (k * SX + n4) * 2;
            uint2 hp, lp;
            hp.x = pack2(v.x, v.y); hp.y = pack2(v.z, v.w);
            __nv_bfloat162 h0 = *(__nv_bfloat162*)&hp.x;
            __nv_bfloat162 h1 = *(__nv_bfloat162*)&hp.y;
            lp.x = pack2lo(v.x, __bfloat162float(h0.x), v.y, __bfloat162float(h0.y));
            lp.y = pack2lo(v.z, __bfloat162float(h1.x), v.w, __bfloat162float(h1.y));
            *(uint2*)(WH + off) = hp;
            *(uint2*)(WL + off) = lp;
        }
    }
    if (tid < 128) {
        int ch = h * 128 + tid;
        scv[tid] = 8.f * log1pf(expf(a_param[ch]));
        b1v[tid] = b_in[ch];
        b2v[tid] = b_a[ch];
    }

    // prefetch x tile 0 into registers
    const int pr = tid >> 5, pc4 = (tid & 31) * 4;
    float4 xr[8];
    #pragma unroll
    for (int i = 0; i < 8; i++)
        xr[i] = *(const float4*)&x[(size_t)(row0 + pr + i * 8) * W_ + h * 128 + pc4];
    __syncthreads();

    const uint32_t xh_b = smem_u32(sm + SM_XH);
    const uint32_t xl_b = smem_u32(sm + SM_XL);
    const uint32_t w_b[2][2] = {
        { smem_u32(sm + SM_W1H), smem_u32(sm + SM_W1L) },
        { smem_u32(sm + SM_W2H), smem_u32(sm + SM_W2L) } };

    const int rw = wid >> 2, cw = wid & 3;
    const int mrow = rw * 32, ncol = cw * 32;

    for (int it = 0; it < 8; it++) {
        // stage x regs -> smem (hi/lo split)
        #pragma unroll
        for (int i = 0; i < 8; i++) {
            float4 v = xr[i];
            uint32_t off = ((pr + i * 8) * SX + pc4) * 2;
            uint2 hp, lp;
            hp.x = pack2(v.x, v.y); hp.y = pack2(v.z, v.w);
            __nv_bfloat162 h0 = *(__nv_bfloat162*)&hp.x;
            __nv_bfloat162 h1 = *(__nv_bfloat162*)&hp.y;
            lp.x = pack2lo(v.x, __bfloat162float(h0.x), v.y, __bfloat162float(h0.y));
            lp.y = pack2lo(v.z, __bfloat162float(h1.x), v.w, __bfloat162float(h1.y));
            *(uint2*)(sm + SM_XH + off) = hp;
            *(uint2*)(sm + SM_XL + off) = lp;
        }
        __syncthreads();

        // prefetch next x tile (overlaps mma loop)
        if (it < 7) {
            #pragma unroll
            for (int i = 0; i < 8; i++)
                xr[i] = *(const float4*)&x[(size_t)(row0 + (it + 1) * 64 + pr + i * 8) * W_ + h * 128 + pc4];
        }

        float C[2][2][4][4];
        #pragma unroll
        for (int g = 0; g < 2; g++)
            #pragma unroll
            for (int m = 0; m < 2; m++)
                #pragma unroll
                for (int n = 0; n < 4; n++)
                    #pragma unroll
                    for (int e = 0; e < 4; e++) C[g][m][n][e] = 0.f;

        #pragma unroll
        for (int kt = 0; kt < 8; kt++) {
            const int k0 = kt * 16;
            uint32_t ah[2][4], al[2][4];
            #pragma unroll
            for (int m = 0; m < 2; m++) {
                uint32_t off = ((mrow + m * 16 + (lane & 15)) * SX + k0 + (lane >> 4) * 8) * 2;
                ldm_x4(ah[m], xh_b + off);
                ldm_x4(al[m], xl_b + off);
            }
            #pragma unroll
            for (int g = 0; g < 2; g++) {
                uint32_t bh[2][4], bl[2][4];
                #pragma unroll
                for (int nn = 0; nn < 2; nn++) {
                    uint32_t off = ((k0 + (lane & 15)) * SX + ncol + nn * 16 + (lane >> 4) * 8) * 2;
                    ldm_x4_t(bh[nn], w_b[g][0] + off);
                    ldm_x4_t(bl[nn], w_b[g][1] + off);
                }
                #pragma unroll
                for (int m = 0; m < 2; m++)
                    #pragma unroll
                    for (int n = 0; n < 4; n++) {
                        const uint32_t* bhp = &bh[n >> 1][(n & 1) * 2];
                        const uint32_t* blp = &bl[n >> 1][(n & 1) * 2];
                        mma16816(C[g][m][n], ah[m], bhp);
                        mma16816(C[g][m][n], ah[m], blp);
                        mma16816(C[g][m][n], al[m], bhp);
                    }
            }
        }

        // ---- epilogue: gates -> g_A, g_NX ----
        #pragma unroll
        for (int m = 0; m < 2; m++) {
            #pragma unroll
            for (int half = 0; half < 2; half++) {
                const int rloc = mrow + m * 16 + (lane >> 2) + half * 8;
                const int grow = row0 + it * 64 + rloc;
                const bool rst = ((grow & (T_ - 1)) == 0);
                #pragma unroll
                for (int n = 0; n < 4; n++) {
                    const int col = ncol + n * 8 + (lane & 3) * 2;
                    float v1a = C[0][m][n][half * 2],     v1b = C[0][m][n][half * 2 + 1];
                    float v2a = C[1][m][n][half * 2],     v2b = C[1][m][n][half * 2 + 1];
                    __nv_bfloat162 xhp = *(__nv_bfloat162*)(sm + SM_XH + (rloc * SX + col) * 2);
                    __nv_bfloat162 xlp = *(__nv_bfloat162*)(sm + SM_XL + (rloc * SX + col) * 2);
                    float x0 = __bfloat162float(xhp.x) + __bfloat162float(xlp.x);
                    float x1 = __bfloat162float(xhp.y) + __bfloat162float(xlp.y);
                    float gx0 = sigm(v1a + b1v[col]),     gx1 = sigm(v1b + b1v[col + 1]);
                    float ga0 = sigm(v2a + b2v[col]),     ga1 = sigm(v2b + b2v[col + 1]);
                    float a0 = __expf(-scv[col] * ga0);
                    float a1 = __expf(-scv[col + 1] * ga1);
                    float m0 = sqrt_ap(fmaxf(0.f, 1.f - a0 * a0));
                    float m1 = sqrt_ap(fmaxf(0.f, 1.f - a1 * a1));
                    if (rst) { a0 = 0.f; a1 = 0.f; m0 = 1.f; m1 = 1.f; }
                    float2 av; av.x = a0; av.y = a1;
                    float2 nv; nv.x = x0 * gx0 * m0; nv.y = x1 * gx1 * m1;
                    size_t gb = (size_t)grow * W_ + h * 128 + col;
                    *(float2*)&g_A [gb] = av;
                    *(float2*)&g_NX[gb] = nv;
                }
            }
        }
        __syncthreads();
    }
}

// ---------------- kernels 2-4: scan / carry / apply ----------------
__global__ void __launch_bounds__(1024) scan_kernel(float* __restrict__ y)
{
    const int c = blockIdx.x, b = blockIdx.y, ch = threadIdx.x;
    size_t base = ((size_t)b * T_ + (size_t)c * TC) * W_ + ch;
    float hv = 0.f, ap = 1.f;
    #pragma unroll 4
    for (int t = 0; t < TC; t++) {
        size_t idx = base + (size_t)t * W_;
        float a = g_A[idx], nx = g_NX[idx];
        hv = fmaf(a, hv, nx);
        ap *= a;
        y[idx] = hv;
        g_A[idx] = ap;
    }
    int sidx = (b * NC + c) * W_ + ch;
    g_Aprod[sidx] = ap;
    g_hlast[sidx] = hv;
}

__global__ void __launch_bounds__(1024) carry_kernel()
{
    const int b = blockIdx.x, ch = threadIdx.x;
    float carry = 0.f;
    for (int c = 0; c < NC; c++) {
        int sidx = (b * NC + c) * W_ + ch;
        g_carry[sidx] = carry;
        carry = fmaf(g_Aprod[sidx], carry, g_hlast[sidx]);
    }
}

__global__ void __launch_bounds__(1024) apply_kernel(float* __restrict__ y)
{
    const int c = blockIdx.x + 1, b = blockIdx.y, ch = threadIdx.x;
    float carry = g_carry[(b * NC + c) * W_ + ch];
    size_t base = ((size_t)b * T_ + (size_t)c * TC) * W_ + ch;
    #pragma unroll 4
    for (int t = 0; t < TC; t++) {
        size_t idx = base + (size_t)t * W_;
        y[idx] = fmaf(g_A[idx], carry, y[idx]);
    }
}

// ---------------------------------------------------------------------------
extern "C" void kernel_launch(void* const* d_in, const int* in_sizes, int n_in,
                              void* d_out, int out_size)
{
    const float* x       = (const float*)d_in[0];
    const float* w_in    = (const float*)d_in[1];
    const float* b_in    = (const float*)d_in[2];
    const float* w_a     = (const float*)d_in[3];
    const float* b_a     = (const float*)d_in[4];
    const float* a_param = (const float*)d_in[5];
    float* y = (float*)d_out;

    cudaFuncSetAttribute(gates_kernel,
                         cudaFuncAttributeMaxDynamicSharedMemorySize, SM_TOTAL);

    gates_kernel<<<dim3(64, H_), 256, SM_TOTAL>>>(x, w_in, b_in, w_a, b_a, a_param);
    scan_kernel <<<dim3(NC, B_), 1024>>>(y);
    carry_kernel<<<B_, 1024>>>();
    apply_kernel<<<dim3(NC - 1, B_), 1024>>>(y);
}

// round 5
// speedup vs baseline: 3.1919x; 1.1993x over previous
#include <cuda_runtime.h>
#include <cuda_bf16.h>
#include <cstdint>
#include <math.h>

#define B_  8
#define T_  4096
#define W_  1024
#define H_  8
#define NCH 8      // chunks per batch (512 steps each)

// ---------------- scratch ----------------
__device__ float g_P [(size_t)B_ * T_ * W_];           // chunk prefix products
__device__ float g_Aprod[B_ * NCH * W_];
__device__ float g_hlast[B_ * NCH * W_];
__device__ float g_carry[B_ * NCH * W_];
__device__ unsigned char g_Wimg[(size_t)H_ * 4 * 32768]; // per head: w1h,w1l,w2h,w2l (swizzled)

// ---------------- smem layout (bytes) ----------------
#define SP        130                       // scan tile row stride (floats)
#define SM_W      0                         // 4 x 32768
#define SM_XH     131072                    // 16384
#define SM_XL     147456                    // 16384
#define SM_SA     163840                    // 64*130*4 = 33280
#define SM_SNX    197120                    // 33280
#define SM_SC     230400
#define SM_B1     230912
#define SM_B2     231424
#define SM_TOTAL  231936

__device__ __forceinline__ uint32_t smem_u32(const void* p) {
    uint32_t a;
    asm("{ .reg .u64 t; cvta.to.shared.u64 t, %1; cvt.u32.u64 %0, t; }" : "=r"(a) : "l"(p));
    return a;
}
// swizzle for 256B-row tiles: XOR row(bits 8..10) into 16B-unit bits 4..6
__device__ __host__ __forceinline__ uint32_t swz(uint32_t o) {
    return o ^ (((o >> 8) & 7u) << 4);
}
__device__ __forceinline__ void ldm_x4(uint32_t* r, uint32_t addr) {
    asm volatile("ldmatrix.sync.aligned.m8n8.x4.shared.b16 {%0,%1,%2,%3}, [%4];"
        : "=r"(r[0]), "=r"(r[1]), "=r"(r[2]), "=r"(r[3]) : "r"(addr));
}
__device__ __forceinline__ void ldm_x4_t(uint32_t* r, uint32_t addr) {
    asm volatile("ldmatrix.sync.aligned.m8n8.x4.trans.shared.b16 {%0,%1,%2,%3}, [%4];"
        : "=r"(r[0]), "=r"(r[1]), "=r"(r[2]), "=r"(r[3]) : "r"(addr));
}
__device__ __forceinline__ void mma16816(float* c, const uint32_t* a, const uint32_t* b) {
    asm volatile("mma.sync.aligned.m16n8k16.row.col.f32.bf16.bf16.f32 "
        "{%0,%1,%2,%3}, {%4,%5,%6,%7}, {%8,%9}, {%0,%1,%2,%3};"
        : "+f"(c[0]), "+f"(c[1]), "+f"(c[2]), "+f"(c[3])
        : "r"(a[0]), "r"(a[1]), "r"(a[2]), "r"(a[3]), "r"(b[0]), "r"(b[1]));
}
__device__ __forceinline__ float sigm(float v) {
    return __fdividef(1.f, 1.f + __expf(-v));
}
__device__ __forceinline__ float sqrt_ap(float v) {
    float r; asm("sqrt.approx.f32 %0, %1;" : "=f"(r) : "f"(v)); return r;
}
__device__ __forceinline__ uint32_t pack2(float a, float b) {
    __nv_bfloat162 t; t.x = __float2bfloat16(a); t.y = __float2bfloat16(b);
    return *(uint32_t*)&t;
}
__device__ __forceinline__ uint32_t pack2lo(float a, float ha, float b, float hb) {
    __nv_bfloat162 t; t.x = __float2bfloat16(a - ha); t.y = __float2bfloat16(b - hb);
    return *(uint32_t*)&t;
}

// ---------------- kernel 0: weight prep ----------------
__global__ void __launch_bounds__(256) wprep_kernel(const float* __restrict__ w_in,
                                                    const float* __restrict__ w_a) {
    const int h = blockIdx.x;
    unsigned char* img = g_Wimg + (size_t)h * 131072;
    #pragma unroll
    for (int g = 0; g < 2; g++) {
        const float* wsrc = (g ? w_a : w_in) + h * 16384;
        unsigned char* WH = img + (size_t)(g * 2 + 0) * 32768;
        unsigned char* WL = img + (size_t)(g * 2 + 1) * 32768;
        for (int idx = threadIdx.x; idx < 4096; idx += 256) {
            int k = idx >> 5, n4 = (idx & 31) * 4;
            float4 v = *(const float4*)&wsrc[k * 128 + n4];
            uint32_t off = swz((uint32_t)k * 256u + (uint32_t)n4 * 2u);
            uint2 hp, lp;
            hp.x = pack2(v.x, v.y); hp.y = pack2(v.z, v.w);
            __nv_bfloat162 h0 = *(__nv_bfloat162*)&hp.x;
            __nv_bfloat162 h1 = *(__nv_bfloat162*)&hp.y;
            lp.x = pack2lo(v.x, __bfloat162float(h0.x), v.y, __bfloat162float(h0.y));
            lp.y = pack2lo(v.z, __bfloat162float(h1.x), v.w, __bfloat162float(h1.y));
            *(uint2*)(WH + off) = hp;
            *(uint2*)(WL + off) = lp;
        }
    }
}

// ---------------------------------------------------------------------------
// kernel 1: gates GEMM + fused chunk-local scan.
// block = (chunk of 512 steps, head). 256 threads, 8 warps.
// ---------------------------------------------------------------------------
__global__ void __launch_bounds__(256, 1) gates_kernel(
    const float* __restrict__ x, const float* __restrict__ b_in,
    const float* __restrict__ b_a, const float* __restrict__ a_param,
    float* __restrict__ y)
{
    extern __shared__ char sm[];
    const int tid = threadIdx.x, wid = tid >> 5, lane = tid & 31;
    const int h = blockIdx.y;
    const int row0 = blockIdx.x * 512;        // blockIdx.x = b*8 + chunk

    float* scv = (float*)(sm + SM_SC);
    float* b1v = (float*)(sm + SM_B1);
    float* b2v = (float*)(sm + SM_B2);
    float* sA  = (float*)(sm + SM_SA);
    float* sNX = (float*)(sm + SM_SNX);

    // copy pre-converted weight images (128KB, L2-resident)
    {
        const float4* src = (const float4*)(g_Wimg + (size_t)h * 131072);
        float4* dst = (float4*)(sm + SM_W);
        #pragma unroll 8
        for (int i = tid; i < 8192; i += 256) dst[i] = src[i];
    }
    if (tid < 128) {
        int ch = h * 128 + tid;
        scv[tid] = 8.f * log1pf(expf(a_param[ch]));
        b1v[tid] = b_in[ch];
        b2v[tid] = b_a[ch];
    }

    // prefetch x tile 0
    const int pr = tid >> 5, pc4 = (tid & 31) * 4;
    float4 xr[8];
    #pragma unroll
    for (int i = 0; i < 8; i++)
        xr[i] = *(const float4*)&x[(size_t)(row0 + pr + i * 8) * W_ + h * 128 + pc4];
    __syncthreads();

    const uint32_t xh_b = smem_u32(sm + SM_XH);
    const uint32_t xl_b = smem_u32(sm + SM_XL);
    const uint32_t wbase = smem_u32(sm + SM_W);

    const int rw = wid >> 2, cw = wid & 3;
    const int mrow = rw * 32, ncol = cw * 32;

    float h_run = 0.f, P_run = 1.f;   // scan carries (tid<128 uses)

    for (int it = 0; it < 8; it++) {
        // ---- stage x -> smem hi/lo (swizzled) ----
        #pragma unroll
        for (int i = 0; i < 8; i++) {
            float4 v = xr[i];
            uint32_t off = swz((uint32_t)(pr + i * 8) * 256u + (uint32_t)pc4 * 2u);
            uint2 hp, lp;
            hp.x = pack2(v.x, v.y); hp.y = pack2(v.z, v.w);
            __nv_bfloat162 h0 = *(__nv_bfloat162*)&hp.x;
            __nv_bfloat162 h1 = *(__nv_bfloat162*)&hp.y;
            lp.x = pack2lo(v.x, __bfloat162float(h0.x), v.y, __bfloat162float(h0.y));
            lp.y = pack2lo(v.z, __bfloat162float(h1.x), v.w, __bfloat162float(h1.y));
            *(uint2*)(sm + SM_XH + off) = hp;
            *(uint2*)(sm + SM_XL + off) = lp;
        }
        __syncthreads();

        if (it < 7) {
            #pragma unroll
            for (int i = 0; i < 8; i++)
                xr[i] = *(const float4*)&x[(size_t)(row0 + (it + 1) * 64 + pr + i * 8) * W_ + h * 128 + pc4];
        }

        // ---- mma: 3-pass split bf16, both gemms ----
        float C[2][2][4][4];
        #pragma unroll
        for (int g = 0; g < 2; g++)
            #pragma unroll
            for (int m = 0; m < 2; m++)
                #pragma unroll
                for (int n = 0; n < 4; n++)
                    #pragma unroll
                    for (int e = 0; e < 4; e++) C[g][m][n][e] = 0.f;

        #pragma unroll
        for (int kt = 0; kt < 8; kt++) {
            const int k0 = kt * 16;
            uint32_t ah[2][4], al[2][4];
            #pragma unroll
            for (int m = 0; m < 2; m++) {
                uint32_t off = swz((uint32_t)(mrow + m * 16 + (lane & 15)) * 256u
                                   + (uint32_t)(k0 + (lane >> 4) * 8) * 2u);
                ldm_x4(ah[m], xh_b + off);
                ldm_x4(al[m], xl_b + off);
            }
            #pragma unroll
            for (int g = 0; g < 2; g++) {
                uint32_t bh[2][4], bl[2][4];
                #pragma unroll
                for (int nn = 0; nn < 2; nn++) {
                    uint32_t off = swz((uint32_t)(k0 + (lane & 15)) * 256u
                                       + (uint32_t)(ncol + nn * 16 + (lane >> 4) * 8) * 2u);
                    ldm_x4_t(bh[nn], wbase + (g * 2 + 0) * 32768 + off);
                    ldm_x4_t(bl[nn], wbase + (g * 2 + 1) * 32768 + off);
                }
                #pragma unroll
                for (int m = 0; m < 2; m++)
                    #pragma unroll
                    for (int n = 0; n < 4; n++) {
                        const uint32_t* bhp = &bh[n >> 1][(n & 1) * 2];
                        const uint32_t* blp = &bl[n >> 1][(n & 1) * 2];
                        mma16816(C[g][m][n], ah[m], bhp);
                        mma16816(C[g][m][n], ah[m], blp);
                        mma16816(C[g][m][n], al[m], bhp);
                    }
            }
        }

        // ---- epilogue: gates -> smem a/nx tiles ----
        #pragma unroll
        for (int m = 0; m < 2; m++) {
            #pragma unroll
            for (int half = 0; half < 2; half++) {
                const int rloc = mrow + m * 16 + (lane >> 2) + half * 8;
                const bool rst = (((row0 + it * 64 + rloc) & (T_ - 1)) == 0);
                #pragma unroll
                for (int n = 0; n < 4; n++) {
                    const int col = ncol + n * 8 + (lane & 3) * 2;
                    float v1a = C[0][m][n][half * 2], v1b = C[0][m][n][half * 2 + 1];
                    float v2a = C[1][m][n][half * 2], v2b = C[1][m][n][half * 2 + 1];
                    uint32_t xoff = swz((uint32_t)rloc * 256u + (uint32_t)col * 2u);
                    __nv_bfloat162 xhp = *(__nv_bfloat162*)(sm + SM_XH + xoff);
                    __nv_bfloat162 xlp = *(__nv_bfloat162*)(sm + SM_XL + xoff);
                    float x0 = __bfloat162float(xhp.x) + __bfloat162float(xlp.x);
                    float x1 = __bfloat162float(xhp.y) + __bfloat162float(xlp.y);
                    float gx0 = sigm(v1a + b1v[col]),     gx1 = sigm(v1b + b1v[col + 1]);
                    float ga0 = sigm(v2a + b2v[col]),     ga1 = sigm(v2b + b2v[col + 1]);
                    float a0 = __expf(-scv[col] * ga0);
                    float a1 = __expf(-scv[col + 1] * ga1);
                    float m0 = sqrt_ap(fmaxf(0.f, 1.f - a0 * a0));
                    float m1 = sqrt_ap(fmaxf(0.f, 1.f - a1 * a1));
                    if (rst) { a0 = 0.f; a1 = 0.f; m0 = 1.f; m1 = 1.f; }
                    float2 av; av.x = a0; av.y = a1;
                    float2 nv; nv.x = x0 * gx0 * m0; nv.y = x1 * gx1 * m1;
                    *(float2*)&sA [rloc * SP + col] = av;
                    *(float2*)&sNX[rloc * SP + col] = nv;
                }
            }
        }
        __syncthreads();

        // ---- chunk-local scan over this tile's 64 steps (one thread/channel) ----
        if (tid < 128) {
            float hv = h_run, pv = P_run;
            #pragma unroll 8
            for (int t = 0; t < 64; t++) {
                float a  = sA [t * SP + tid];
                float nx = sNX[t * SP + tid];
                hv = fmaf(a, hv, nx);
                pv *= a;
                sNX[t * SP + tid] = hv;   // y_local
                sA [t * SP + tid] = pv;   // chunk prefix product
            }
            h_run = hv; P_run = pv;
        }
        __syncthreads();

        // ---- copy out y_local and P (coalesced float2) ----
        {
            const size_t gtile = (size_t)(row0 + it * 64) * W_ + h * 128;
            #pragma unroll 4
            for (int u = tid; u < 4096; u += 256) {
                int t = u >> 6, cp = (u & 63) * 2;
                size_t ga = gtile + (size_t)t * W_ + cp;
                *(float2*)&y  [ga] = *(float2*)&sNX[t * SP + cp];
                *(float2*)&g_P[ga] = *(float2*)&sA [t * SP + cp];
            }
        }
        // no barrier needed: next staging touches only X smem
    }

    if (tid < 128) {
        int sidx = blockIdx.x * W_ + h * 128 + tid;
        g_Aprod[sidx] = P_run;
        g_hlast[sidx] = h_run;
    }
}

// ---------------- kernel 2: cross-chunk carry scan (8 chunks/batch) ----------
__global__ void __launch_bounds__(1024) carry_kernel()
{
    const int b = blockIdx.x, ch = threadIdx.x;
    float carry = 0.f;
    #pragma unroll
    for (int c = 0; c < NCH; c++) {
        int sidx = (b * NCH + c) * W_ + ch;
        g_carry[sidx] = carry;
        carry = fmaf(g_Aprod[sidx], carry, g_hlast[sidx]);
    }
}

// ---------------- kernel 3: apply carries. grid (56, 8) x 1024 ----------
__global__ void __launch_bounds__(1024) apply_kernel(float* __restrict__ y)
{
    const int sub = blockIdx.x & 7;
    const int c   = (blockIdx.x >> 3) + 1;
    const int b   = blockIdx.y;
    const int ch  = threadIdx.x;
    float carry = g_carry[(b * NCH + c) * W_ + ch];
    size_t base = ((size_t)b * T_ + (size_t)c * 512 + (size_t)sub * 64) * W_ + ch;
    #pragma unroll 8
    for (int t = 0; t < 64; t++) {
        size_t idx = base + (size_t)t * W_;
        y[idx] = fmaf(g_P[idx], carry, y[idx]);
    }
}

// ---------------------------------------------------------------------------
extern "C" void kernel_launch(void* const* d_in, const int* in_sizes, int n_in,
                              void* d_out, int out_size)
{
    const float* x       = (const float*)d_in[0];
    const float* w_in    = (const float*)d_in[1];
    const float* b_in    = (const float*)d_in[2];
    const float* w_a     = (const float*)d_in[3];
    const float* b_a     = (const float*)d_in[4];
    const float* a_param = (const float*)d_in[5];
    float* y = (float*)d_out;

    cudaFuncSetAttribute(gates_kernel,
                         cudaFuncAttributeMaxDynamicSharedMemorySize, SM_TOTAL);

    wprep_kernel<<<H_, 256>>>(w_in, w_a);
    gates_kernel<<<dim3(B_ * NCH, H_), 256, SM_TOTAL>>>(x, b_in, b_a, a_param, y);
    carry_kernel<<<B_, 1024>>>();
    apply_kernel<<<dim3(56, B_), 1024>>>(y);
}

// round 7
// speedup vs baseline: 4.6475x; 1.4560x over previous
#include <cuda_runtime.h>
#include <cuda_fp16.h>
#include <cstdint>
#include <math.h>

#define B_  8
#define T_  4096
#define W_  1024
#define H_  8
#define NCH 8      // chunks per batch (512 steps each)

// ---------------- scratch ----------------
__device__ float g_P [(size_t)B_ * T_ * W_];           // chunk prefix products
__device__ float g_Aprod[B_ * NCH * W_];
__device__ float g_hlast[B_ * NCH * W_];
__device__ float g_carry[B_ * NCH * W_];
__device__ unsigned char g_Wimg[(size_t)H_ * 2 * 32768]; // per head: w1,w2 fp16 (swizzled)

// ---------------- smem layout (bytes) ----------------
#define SP        130                       // scan tile row stride (floats)
#define SM_W      0                         // 2 x 32768 (fp16 w1,w2)
#define SM_XH     65536                     // 16384 (fp16 hi)
#define SM_XL     81920                     // 16384 (fp16 residual)
#define SM_SA     98304                     // 64*130*4 = 33280
#define SM_SNX    131584                    // 33280
#define SM_SC     164864
#define SM_B1     165376
#define SM_B2     165888
#define SM_TOTAL  166400

__device__ __forceinline__ uint32_t smem_u32(const void* p) {
    uint32_t a;
    asm("{ .reg .u64 t; cvta.to.shared.u64 t, %1; cvt.u32.u64 %0, t; }" : "=r"(a) : "l"(p));
    return a;
}
// swizzle for 256B rows: XOR row bits (8..10) into 16B-unit bits (4..6)
__device__ __forceinline__ uint32_t swz(uint32_t o) {
    return o ^ (((o >> 8) & 7u) << 4);
}
__device__ __forceinline__ void ldm_x4(uint32_t* r, uint32_t addr) {
    asm volatile("ldmatrix.sync.aligned.m8n8.x4.shared.b16 {%0,%1,%2,%3}, [%4];"
        : "=r"(r[0]), "=r"(r[1]), "=r"(r[2]), "=r"(r[3]) : "r"(addr));
}
__device__ __forceinline__ void ldm_x4_t(uint32_t* r, uint32_t addr) {
    asm volatile("ldmatrix.sync.aligned.m8n8.x4.trans.shared.b16 {%0,%1,%2,%3}, [%4];"
        : "=r"(r[0]), "=r"(r[1]), "=r"(r[2]), "=r"(r[3]) : "r"(addr));
}
__device__ __forceinline__ void mma_f16(float* c, const uint32_t* a, const uint32_t* b) {
    asm volatile("mma.sync.aligned.m16n8k16.row.col.f32.f16.f16.f32 "
        "{%0,%1,%2,%3}, {%4,%5,%6,%7}, {%8,%9}, {%0,%1,%2,%3};"
        : "+f"(c[0]), "+f"(c[1]), "+f"(c[2]), "+f"(c[3])
        : "r"(a[0]), "r"(a[1]), "r"(a[2]), "r"(a[3]), "r"(b[0]), "r"(b[1]));
}
__device__ __forceinline__ float sigm(float v) {
    return __fdividef(1.f, 1.f + __expf(-v));
}
__device__ __forceinline__ float sqrt_ap(float v) {
    float r; asm("sqrt.approx.f32 %0, %1;" : "=f"(r) : "f"(v)); return r;
}
__device__ __forceinline__ uint32_t packh2(float a, float b) {
    __half2 t; t.x = __float2half_rn(a); t.y = __float2half_rn(b);
    return *(uint32_t*)&t;
}

// ---------------- kernel 0: weight prep (fp16, swizzled) ----------------
__global__ void __launch_bounds__(256) wprep_kernel(const float* __restrict__ w_in,
                                                    const float* __restrict__ w_a) {
    const int h = blockIdx.x;
    unsigned char* img = g_Wimg + (size_t)h * 65536;
    #pragma unroll
    for (int g = 0; g < 2; g++) {
        const float* wsrc = (g ? w_a : w_in) + h * 16384;
        unsigned char* WH = img + (size_t)g * 32768;
        for (int idx = threadIdx.x; idx < 4096; idx += 256) {
            int k = idx >> 5, n4 = (idx & 31) * 4;
            float4 v = *(const float4*)&wsrc[k * 128 + n4];
            uint32_t off = swz((uint32_t)k * 256u + (uint32_t)n4 * 2u);
            uint2 hp;
            hp.x = packh2(v.x, v.y); hp.y = packh2(v.z, v.w);
            *(uint2*)(WH + off) = hp;
        }
    }
}

// ---------------------------------------------------------------------------
// kernel 1: gates GEMM (fp16 single-pass) + fused chunk-local scan.
// block = (chunk of 512 steps, head). 512 threads, 16 warps, warp tile 16x32.
// ---------------------------------------------------------------------------
__global__ void __launch_bounds__(512, 1) gates_kernel(
    const float* __restrict__ x, const float* __restrict__ b_in,
    const float* __restrict__ b_a, const float* __restrict__ a_param,
    float* __restrict__ y)
{
    extern __shared__ char sm[];
    const int tid = threadIdx.x, wid = tid >> 5, lane = tid & 31;
    const int h = blockIdx.y;
    const int row0 = blockIdx.x * 512;        // blockIdx.x = b*NCH + chunk

    float* scv = (float*)(sm + SM_SC);
    float* b1v = (float*)(sm + SM_B1);
    float* b2v = (float*)(sm + SM_B2);
    float* sA  = (float*)(sm + SM_SA);
    float* sNX = (float*)(sm + SM_SNX);

    // copy fp16 weight images (64KB, L2-resident)
    {
        const float4* src = (const float4*)(g_Wimg + (size_t)h * 65536);
        float4* dst = (float4*)(sm + SM_W);
        #pragma unroll 8
        for (int i = tid; i < 4096; i += 512) dst[i] = src[i];
    }
    if (tid < 128) {
        int ch = h * 128 + tid;
        scv[tid] = 8.f * log1pf(expf(a_param[ch]));
        b1v[tid] = b_in[ch];
        b2v[tid] = b_a[ch];
    }

    // prefetch x tile 0 (each thread: 4 float4)
    const int pr = tid >> 5, pc4 = (tid & 31) * 4;
    float4 xr[4];
    #pragma unroll
    for (int i = 0; i < 4; i++)
        xr[i] = *(const float4*)&x[(size_t)(row0 + pr + i * 16) * W_ + h * 128 + pc4];
    __syncthreads();

    const uint32_t xh_b  = smem_u32(sm + SM_XH);
    const uint32_t wbase = smem_u32(sm + SM_W);

    const int cw = wid >> 2, rw = wid & 3;      // rw-groups share B frags
    const int mrow = rw * 16, ncol = cw * 32;

    float h_run = 0.f, P_run = 1.f;   // scan carries (tid<128)

    for (int it = 0; it < 8; it++) {
        // ---- stage x -> smem fp16 hi + residual (swizzled) ----
        #pragma unroll
        for (int i = 0; i < 4; i++) {
            float4 v = xr[i];
            uint32_t off = swz((uint32_t)(pr + i * 16) * 256u + (uint32_t)pc4 * 2u);
            uint2 hp, lp;
            hp.x = packh2(v.x, v.y); hp.y = packh2(v.z, v.w);
            __half2 h0 = *(__half2*)&hp.x;
            __half2 h1 = *(__half2*)&hp.y;
            lp.x = packh2(v.x - __half2float(h0.x), v.y - __half2float(h0.y));
            lp.y = packh2(v.z - __half2float(h1.x), v.w - __half2float(h1.y));
            *(uint2*)(sm + SM_XH + off) = hp;
            *(uint2*)(sm + SM_XL + off) = lp;
        }
        __syncthreads();

        if (it < 7) {
            #pragma unroll
            for (int i = 0; i < 4; i++)
                xr[i] = *(const float4*)&x[(size_t)(row0 + (it + 1) * 64 + pr + i * 16) * W_ + h * 128 + pc4];
        }

        // ---- mma: single-pass fp16, both gemms ----
        float C[2][4][4];
        #pragma unroll
        for (int g = 0; g < 2; g++)
            #pragma unroll
            for (int n = 0; n < 4; n++)
                #pragma unroll
                for (int e = 0; e < 4; e++) C[g][n][e] = 0.f;

        #pragma unroll
        for (int kt = 0; kt < 8; kt++) {
            const int k0 = kt * 16;
            uint32_t ah[4];
            {
                uint32_t off = swz((uint32_t)(mrow + (lane & 15)) * 256u
                                   + (uint32_t)(k0 + (lane >> 4) * 8) * 2u);
                ldm_x4(ah, xh_b + off);
            }
            #pragma unroll
            for (int g = 0; g < 2; g++) {
                uint32_t bh[2][4];
                #pragma unroll
                for (int nn = 0; nn < 2; nn++) {
                    uint32_t off = swz((uint32_t)(k0 + (lane & 15)) * 256u
                                       + (uint32_t)(ncol + nn * 16 + (lane >> 4) * 8) * 2u);
                    ldm_x4_t(bh[nn], wbase + g * 32768 + off);
                }
                #pragma unroll
                for (int n = 0; n < 4; n++)
                    mma_f16(C[g][n], ah, &bh[n >> 1][(n & 1) * 2]);
            }
        }

        // ---- epilogue: gates -> smem a/nx tiles ----
        #pragma unroll
        for (int half = 0; half < 2; half++) {
            const int rloc = mrow + (lane >> 2) + half * 8;
            const bool rst = (((row0 + it * 64 + rloc) & (T_ - 1)) == 0);
            #pragma unroll
            for (int n = 0; n < 4; n++) {
                const int col = ncol + n * 8 + (lane & 3) * 2;
                float v1a = C[0][n][half * 2], v1b = C[0][n][half * 2 + 1];
                float v2a = C[1][n][half * 2], v2b = C[1][n][half * 2 + 1];
                uint32_t xoff = swz((uint32_t)rloc * 256u + (uint32_t)col * 2u);
                __half2 xhp = *(__half2*)(sm + SM_XH + xoff);
                __half2 xlp = *(__half2*)(sm + SM_XL + xoff);
                float x0 = __half2float(xhp.x) + __half2float(xlp.x);
                float x1 = __half2float(xhp.y) + __half2float(xlp.y);
                float gx0 = sigm(v1a + b1v[col]),     gx1 = sigm(v1b + b1v[col + 1]);
                float ga0 = sigm(v2a + b2v[col]),     ga1 = sigm(v2b + b2v[col + 1]);
                float a0 = __expf(-scv[col] * ga0);
                float a1 = __expf(-scv[col + 1] * ga1);
                float m0 = sqrt_ap(fmaxf(0.f, 1.f - a0 * a0));
                float m1 = sqrt_ap(fmaxf(0.f, 1.f - a1 * a1));
                if (rst) { a0 = 0.f; a1 = 0.f; m0 = 1.f; m1 = 1.f; }
                float2 av; av.x = a0; av.y = a1;
                float2 nv; nv.x = x0 * gx0 * m0; nv.y = x1 * gx1 * m1;
                *(float2*)&sA [rloc * SP + col] = av;
                *(float2*)&sNX[rloc * SP + col] = nv;
            }
        }
        __syncthreads();

        // ---- chunk-local scan over 64 steps (one thread/channel) ----
        if (tid < 128) {
            float hv = h_run, pv = P_run;
            #pragma unroll 8
            for (int t = 0; t < 64; t++) {
                float a  = sA [t * SP + tid];
                float nx = sNX[t * SP + tid];
                hv = fmaf(a, hv, nx);
                pv *= a;
                sNX[t * SP + tid] = hv;   // y_local
                sA [t * SP + tid] = pv;   // chunk prefix product
            }
            h_run = hv; P_run = pv;
        }
        __syncthreads();

        // ---- copy out y_local and P (coalesced float2); overlaps next staging ----
        {
            const size_t gtile = (size_t)(row0 + it * 64) * W_ + h * 128;
            #pragma unroll 8
            for (int u = tid; u < 4096; u += 512) {
                int t = u >> 6, cp = (u & 63) * 2;
                size_t ga = gtile + (size_t)t * W_ + cp;
                *(float2*)&y  [ga] = *(float2*)&sNX[t * SP + cp];
                *(float2*)&g_P[ga] = *(float2*)&sA [t * SP + cp];
            }
        }
    }

    if (tid < 128) {
        int sidx = blockIdx.x * W_ + h * 128 + tid;
        g_Aprod[sidx] = P_run;
        g_hlast[sidx] = h_run;
    }
}

// ---------------- kernel 2: cross-chunk carry scan ----------------
__global__ void __launch_bounds__(1024) carry_kernel()
{
    const int b = blockIdx.x, ch = threadIdx.x;
    float carry = 0.f;
    #pragma unroll
    for (int c = 0; c < NCH; c++) {
        int sidx = (b * NCH + c) * W_ + ch;
        g_carry[sidx] = carry;
        carry = fmaf(g_Aprod[sidx], carry, g_hlast[sidx]);
    }
}

// ---------------- kernel 3: apply carries ----------------
__global__ void __launch_bounds__(1024) apply_kernel(float* __restrict__ y)
{
    const int sub = blockIdx.x & 7;
    const int c   = (blockIdx.x >> 3) + 1;
    const int b   = blockIdx.y;
    const int ch  = threadIdx.x;
    float carry = g_carry[(b * NCH + c) * W_ + ch];
    size_t base = ((size_t)b * T_ + (size_t)c * 512 + (size_t)sub * 64) * W_ + ch;
    #pragma unroll 8
    for (int t = 0; t < 64; t++) {
        size_t idx = base + (size_t)t * W_;
        y[idx] = fmaf(g_P[idx], carry, y[idx]);
    }
}

// ---------------------------------------------------------------------------
extern "C" void kernel_launch(void* const* d_in, const int* in_sizes, int n_in,
                              void* d_out, int out_size)
{
    const float* x       = (const float*)d_in[0];
    const float* w_in    = (const float*)d_in[1];
    const float* b_in    = (const float*)d_in[2];
    const float* w_a     = (const float*)d_in[3];
    const float* b_a     = (const float*)d_in[4];
    const float* a_param = (const float*)d_in[5];
    float* y = (float*)d_out;

    cudaFuncSetAttribute(gates_kernel,
                         cudaFuncAttributeMaxDynamicSharedMemorySize, SM_TOTAL);

    wprep_kernel<<<H_, 256>>>(w_in, w_a);
    gates_kernel<<<dim3(B_ * NCH, H_), 512, SM_TOTAL>>>(x, b_in, b_a, a_param, y);
    carry_kernel<<<B_, 1024>>>();
    apply_kernel<<<dim3(56, B_), 1024>>>(y);
}

// round 8
// speedup vs baseline: 4.9665x; 1.0686x over previous
#include <cuda_runtime.h>
#include <cuda_fp16.h>
#include <cstdint>
#include <math.h>

#define B_  8
#define T_  4096
#define W_  1024
#define H_  8
#define NCH 8      // chunks per batch (512 steps each)

// ---------------- scratch ----------------
__device__ float g_P [(size_t)B_ * T_ * W_];           // chunk prefix products
__device__ float g_Aprod[B_ * NCH * W_];
__device__ float g_hlast[B_ * NCH * W_];
__device__ float g_carry[B_ * NCH * W_];
__device__ unsigned char g_Wimg[(size_t)H_ * 2 * 32768]; // per head: w1,w2 fp16 (swizzled)

// ---------------- smem layout (bytes) ----------------
#define SP        130                       // scan tile row stride (floats)
#define SM_W      0                         // 2 x 32768 (fp16 w1,w2)
#define SM_XH     65536                     // 16384
#define SM_XL     81920                     // 16384
#define SM_SA     98304                     // 64*130*4 = 33280
#define SM_SNX    131584                    // 33280
#define SM_SC     164864                    // 512
#define SM_B1     165376
#define SM_B2     165888
#define SM_SEGA   166400                    // 8*128*4 = 4096
#define SM_SEGH   170496                    // 4096
#define SM_HRUN   174592                    // 2*128*4 = 1024 (parity buffers)
#define SM_PRUN   175616                    // 1024
#define SM_TOTAL  176640

__device__ __forceinline__ uint32_t smem_u32(const void* p) {
    uint32_t a;
    asm("{ .reg .u64 t; cvta.to.shared.u64 t, %1; cvt.u32.u64 %0, t; }" : "=r"(a) : "l"(p));
    return a;
}
__device__ __forceinline__ uint32_t swz(uint32_t o) {
    return o ^ (((o >> 8) & 7u) << 4);
}
__device__ __forceinline__ void ldm_x4(uint32_t* r, uint32_t addr) {
    asm volatile("ldmatrix.sync.aligned.m8n8.x4.shared.b16 {%0,%1,%2,%3}, [%4];"
        : "=r"(r[0]), "=r"(r[1]), "=r"(r[2]), "=r"(r[3]) : "r"(addr));
}
__device__ __forceinline__ void ldm_x4_t(uint32_t* r, uint32_t addr) {
    asm volatile("ldmatrix.sync.aligned.m8n8.x4.trans.shared.b16 {%0,%1,%2,%3}, [%4];"
        : "=r"(r[0]), "=r"(r[1]), "=r"(r[2]), "=r"(r[3]) : "r"(addr));
}
__device__ __forceinline__ void mma_f16(float* c, const uint32_t* a, const uint32_t* b) {
    asm volatile("mma.sync.aligned.m16n8k16.row.col.f32.f16.f16.f32 "
        "{%0,%1,%2,%3}, {%4,%5,%6,%7}, {%8,%9}, {%0,%1,%2,%3};"
        : "+f"(c[0]), "+f"(c[1]), "+f"(c[2]), "+f"(c[3])
        : "r"(a[0]), "r"(a[1]), "r"(a[2]), "r"(a[3]), "r"(b[0]), "r"(b[1]));
}
// sigmoid(v) = 0.5 + 0.5*tanh(v/2): single MUFU
__device__ __forceinline__ float sigm(float v) {
    float t;
    asm("tanh.approx.f32 %0, %1;" : "=f"(t) : "f"(v * 0.5f));
    return fmaf(0.5f, t, 0.5f);
}
__device__ __forceinline__ float sqrt_ap(float v) {
    float r; asm("sqrt.approx.f32 %0, %1;" : "=f"(r) : "f"(v)); return r;
}
__device__ __forceinline__ uint32_t packh2(float a, float b) {
    __half2 t; t.x = __float2half_rn(a); t.y = __float2half_rn(b);
    return *(uint32_t*)&t;
}

// ---------------- kernel 0: weight prep (fp16, swizzled) ----------------
__global__ void __launch_bounds__(256) wprep_kernel(const float* __restrict__ w_in,
                                                    const float* __restrict__ w_a) {
    const int h = blockIdx.x;
    unsigned char* img = g_Wimg + (size_t)h * 65536;
    #pragma unroll
    for (int g = 0; g < 2; g++) {
        const float* wsrc = (g ? w_a : w_in) + h * 16384;
        unsigned char* WH = img + (size_t)g * 32768;
        for (int idx = threadIdx.x; idx < 4096; idx += 256) {
            int k = idx >> 5, n4 = (idx & 31) * 4;
            float4 v = *(const float4*)&wsrc[k * 128 + n4];
            uint32_t off = swz((uint32_t)k * 256u + (uint32_t)n4 * 2u);
            uint2 hp;
            hp.x = packh2(v.x, v.y); hp.y = packh2(v.z, v.w);
            *(uint2*)(WH + off) = hp;
        }
    }
}

// ---------------------------------------------------------------------------
// kernel 1: gates GEMM + fused segmented chunk-local scan. 512 threads.
// ---------------------------------------------------------------------------
__global__ void __launch_bounds__(512, 1) gates_kernel(
    const float* __restrict__ x, const float* __restrict__ b_in,
    const float* __restrict__ b_a, const float* __restrict__ a_param,
    float* __restrict__ y)
{
    extern __shared__ char sm[];
    const int tid = threadIdx.x, wid = tid >> 5, lane = tid & 31;
    const int h = blockIdx.y;
    const int row0 = blockIdx.x * 512;        // blockIdx.x = b*NCH + chunk

    float* scv  = (float*)(sm + SM_SC);
    float* b1v  = (float*)(sm + SM_B1);
    float* b2v  = (float*)(sm + SM_B2);
    float* sA   = (float*)(sm + SM_SA);
    float* sNX  = (float*)(sm + SM_SNX);
    float* sgA  = (float*)(sm + SM_SEGA);
    float* sgH  = (float*)(sm + SM_SEGH);
    float* hrun = (float*)(sm + SM_HRUN);
    float* prun = (float*)(sm + SM_PRUN);

    // copy fp16 weight images (64KB, L2-resident)
    {
        const float4* src = (const float4*)(g_Wimg + (size_t)h * 65536);
        float4* dst = (float4*)(sm + SM_W);
        #pragma unroll 8
        for (int i = tid; i < 4096; i += 512) dst[i] = src[i];
    }
    if (tid < 128) {
        int ch = h * 128 + tid;
        scv[tid] = 8.f * log1pf(expf(a_param[ch]));
        b1v[tid] = b_in[ch];
        b2v[tid] = b_a[ch];
    }
    if (tid < 64) {   // init carry parity-0 buffers
        float2 z; z.x = 0.f; z.y = 0.f;
        float2 o; o.x = 1.f; o.y = 1.f;
        *(float2*)&hrun[tid * 2] = z;
        *(float2*)&prun[tid * 2] = o;
    }

    // prefetch x tile 0
    const int pr = tid >> 5, pc4 = (tid & 31) * 4;
    float4 xr[4];
    #pragma unroll
    for (int i = 0; i < 4; i++)
        xr[i] = *(const float4*)&x[(size_t)(row0 + pr + i * 16) * W_ + h * 128 + pc4];
    __syncthreads();

    const uint32_t xh_b  = smem_u32(sm + SM_XH);
    const uint32_t wbase = smem_u32(sm + SM_W);

    const int cw = wid >> 2, rw = wid & 3;
    const int mrow = rw * 16, ncol = cw * 32;
    const int cp  = (tid & 63) * 2;           // channel pair for scan
    const int seg = tid >> 6;                 // 8 segs of 8 steps

    for (int it = 0; it < 8; it++) {
        const int p = it & 1;
        // ---- stage x -> smem fp16 hi + residual (swizzled) ----
        #pragma unroll
        for (int i = 0; i < 4; i++) {
            float4 v = xr[i];
            uint32_t off = swz((uint32_t)(pr + i * 16) * 256u + (uint32_t)pc4 * 2u);
            uint2 hp, lp;
            hp.x = packh2(v.x, v.y); hp.y = packh2(v.z, v.w);
            __half2 h0 = *(__half2*)&hp.x;
            __half2 h1 = *(__half2*)&hp.y;
            lp.x = packh2(v.x - __half2float(h0.x), v.y - __half2float(h0.y));
            lp.y = packh2(v.z - __half2float(h1.x), v.w - __half2float(h1.y));
            *(uint2*)(sm + SM_XH + off) = hp;
            *(uint2*)(sm + SM_XL + off) = lp;
        }
        __syncthreads();

        if (it < 7) {
            #pragma unroll
            for (int i = 0; i < 4; i++)
                xr[i] = *(const float4*)&x[(size_t)(row0 + (it + 1) * 64 + pr + i * 16) * W_ + h * 128 + pc4];
        }

        // ---- mma: single-pass fp16, both gemms ----
        float C[2][4][4];
        #pragma unroll
        for (int g = 0; g < 2; g++)
            #pragma unroll
            for (int n = 0; n < 4; n++)
                #pragma unroll
                for (int e = 0; e < 4; e++) C[g][n][e] = 0.f;

        #pragma unroll
        for (int kt = 0; kt < 8; kt++) {
            const int k0 = kt * 16;
            uint32_t ah[4];
            {
                uint32_t off = swz((uint32_t)(mrow + (lane & 15)) * 256u
                                   + (uint32_t)(k0 + (lane >> 4) * 8) * 2u);
                ldm_x4(ah, xh_b + off);
            }
            #pragma unroll
            for (int g = 0; g < 2; g++) {
                uint32_t bh[2][4];
                #pragma unroll
                for (int nn = 0; nn < 2; nn++) {
                    uint32_t off = swz((uint32_t)(k0 + (lane & 15)) * 256u
                                       + (uint32_t)(ncol + nn * 16 + (lane >> 4) * 8) * 2u);
                    ldm_x4_t(bh[nn], wbase + g * 32768 + off);
                }
                #pragma unroll
                for (int n = 0; n < 4; n++)
                    mma_f16(C[g][n], ah, &bh[n >> 1][(n & 1) * 2]);
            }
        }

        // ---- epilogue: gates -> smem a/nx tiles ----
        #pragma unroll
        for (int half = 0; half < 2; half++) {
            const int rloc = mrow + (lane >> 2) + half * 8;
            const bool rst = (((row0 + it * 64 + rloc) & (T_ - 1)) == 0);
            #pragma unroll
            for (int n = 0; n < 4; n++) {
                const int col = ncol + n * 8 + (lane & 3) * 2;
                float v1a = C[0][n][half * 2], v1b = C[0][n][half * 2 + 1];
                float v2a = C[1][n][half * 2], v2b = C[1][n][half * 2 + 1];
                uint32_t xoff = swz((uint32_t)rloc * 256u + (uint32_t)col * 2u);
                __half2 xhp = *(__half2*)(sm + SM_XH + xoff);
                __half2 xlp = *(__half2*)(sm + SM_XL + xoff);
                float x0 = __half2float(xhp.x) + __half2float(xlp.x);
                float x1 = __half2float(xhp.y) + __half2float(xlp.y);
                float gx0 = sigm(v1a + b1v[col]),     gx1 = sigm(v1b + b1v[col + 1]);
                float ga0 = sigm(v2a + b2v[col]),     ga1 = sigm(v2b + b2v[col + 1]);
                float a0 = __expf(-scv[col] * ga0);
                float a1 = __expf(-scv[col + 1] * ga1);
                float m0 = sqrt_ap(fmaxf(0.f, 1.f - a0 * a0));
                float m1 = sqrt_ap(fmaxf(0.f, 1.f - a1 * a1));
                if (rst) { a0 = 0.f; a1 = 0.f; m0 = 1.f; m1 = 1.f; }
                float2 av; av.x = a0; av.y = a1;
                float2 nv; nv.x = x0 * gx0 * m0; nv.y = x1 * gx1 * m1;
                *(float2*)&sA [rloc * SP + col] = av;
                *(float2*)&sNX[rloc * SP + col] = nv;
            }
        }
        __syncthreads();

        // ---- phase 1: 8-step local scan in registers, publish seg summaries ----
        float2 yl[8], pl[8];
        float2 hv; hv.x = 0.f; hv.y = 0.f;
        float2 pv; pv.x = 1.f; pv.y = 1.f;
        const int t0 = seg * 8;
        #pragma unroll
        for (int t = 0; t < 8; t++) {
            float2 a  = *(float2*)&sA [(t0 + t) * SP + cp];
            float2 nx = *(float2*)&sNX[(t0 + t) * SP + cp];
            hv.x = fmaf(a.x, hv.x, nx.x); hv.y = fmaf(a.y, hv.y, nx.y);
            pv.x *= a.x;                  pv.y *= a.y;
            yl[t] = hv; pl[t] = pv;
        }
        *(float2*)&sgA[seg * 128 + cp] = pv;
        *(float2*)&sgH[seg * 128 + cp] = hv;
        __syncthreads();

        // ---- phase 2+3: fold inbound carry, fix + store directly to gmem ----
        float2 cih = *(float2*)&hrun[p * 128 + cp];
        float2 cip = *(float2*)&prun[p * 128 + cp];
        for (int s = 0; s < seg; s++) {          // warp-uniform trip count
            float2 A  = *(float2*)&sgA[s * 128 + cp];
            float2 Hh = *(float2*)&sgH[s * 128 + cp];
            cih.x = fmaf(A.x, cih.x, Hh.x); cih.y = fmaf(A.y, cih.y, Hh.y);
            cip.x *= A.x;                   cip.y *= A.y;
        }
        if (seg == 7) {                          // publish next-iter carries
            float2 nh, np;
            nh.x = fmaf(pv.x, cih.x, hv.x); nh.y = fmaf(pv.y, cih.y, hv.y);
            np.x = cip.x * pv.x;            np.y = cip.y * pv.y;
            *(float2*)&hrun[(p ^ 1) * 128 + cp] = nh;
            *(float2*)&prun[(p ^ 1) * 128 + cp] = np;
        }
        {
            const size_t gtile = (size_t)(row0 + it * 64 + t0) * W_ + h * 128 + cp;
            #pragma unroll
            for (int t = 0; t < 8; t++) {
                float2 yv, Pv;
                yv.x = fmaf(pl[t].x, cih.x, yl[t].x);
                yv.y = fmaf(pl[t].y, cih.y, yl[t].y);
                Pv.x = pl[t].x * cip.x;
                Pv.y = pl[t].y * cip.y;
                *(float2*)&y  [gtile + (size_t)t * W_] = yv;
                *(float2*)&g_P[gtile + (size_t)t * W_] = Pv;
            }
        }
        // next iter's stage sync orders phase2+3 reads before smem reuse
    }

    __syncthreads();
    if (tid < 64) {   // final carries live in parity 0 (after 8 iters)
        int sidx = blockIdx.x * W_ + h * 128 + cp;
        *(float2*)&g_hlast[sidx] = *(float2*)&hrun[cp];
        *(float2*)&g_Aprod[sidx] = *(float2*)&prun[cp];
    }
}

// ---------------- kernel 2: cross-chunk carry scan ----------------
__global__ void __launch_bounds__(1024) carry_kernel()
{
    const int b = blockIdx.x, ch = threadIdx.x;
    float carry = 0.f;
    #pragma unroll
    for (int c = 0; c < NCH; c++) {
        int sidx = (b * NCH + c) * W_ + ch;
        g_carry[sidx] = carry;
        carry = fmaf(g_Aprod[sidx], carry, g_hlast[sidx]);
    }
}

// ---------------- kernel 3: apply carries ----------------
__global__ void __launch_bounds__(1024) apply_kernel(float* __restrict__ y)
{
    const int sub = blockIdx.x & 7;
    const int c   = (blockIdx.x >> 3) + 1;
    const int b   = blockIdx.y;
    const int ch  = threadIdx.x;
    float carry = g_carry[(b * NCH + c) * W_ + ch];
    size_t base = ((size_t)b * T_ + (size_t)c * 512 + (size_t)sub * 64) * W_ + ch;
    #pragma unroll 8
    for (int t = 0; t < 64; t++) {
        size_t idx = base + (size_t)t * W_;
        y[idx] = fmaf(g_P[idx], carry, y[idx]);
    }
}

// ---------------------------------------------------------------------------
extern "C" void kernel_launch(void* const* d_in, const int* in_sizes, int n_in,
                              void* d_out, int out_size)
{
    const float* x       = (const float*)d_in[0];
    const float* w_in    = (const float*)d_in[1];
    const float* b_in    = (const float*)d_in[2];
    const float* w_a     = (const float*)d_in[3];
    const float* b_a     = (const float*)d_in[4];
    const float* a_param = (const float*)d_in[5];
    float* y = (float*)d_out;

    cudaFuncSetAttribute(gates_kernel,
                         cudaFuncAttributeMaxDynamicSharedMemorySize, SM_TOTAL);

    wprep_kernel<<<H_, 256>>>(w_in, w_a);
    gates_kernel<<<dim3(B_ * NCH, H_), 512, SM_TOTAL>>>(x, b_in, b_a, a_param, y);
    carry_kernel<<<B_, 1024>>>();
    apply_kernel<<<dim3(56, B_), 1024>>>(y);
}